// round 6
// baseline (speedup 1.0000x reference)
#include <cuda_runtime.h>
#include <cstdint>

#define NN 100000
#define EE 3200000
#define PE 3300000   // padded edge capacity (EE + <=1 per node)
#define CC 32
#define LL 4
#define GG 512
#define XDIM 8
#define EDIM 4

#define QSTEP 0.0009765625f   // 2^-10
#define QINV  1024.0f
#define QMAXV (32.0f - 0.0009765625f)
#define QMINV (-32.0f)
#define BN_EPS_F 1e-5f
#define GEN_EPS_F 1e-7f
#define LOG2E_F 1.4426950408889634f

// ---------------- scratch (device globals; no allocation allowed) -------------
__device__ float d_h [NN * CC];            // node features
__device__ float d_hb[NN * CC];            // (h + D_bne + eps) * t[l]*log2e
__device__ float d_h2[NN * CC];            // h + agg
__device__ short d_eq[(size_t)PE * CC];    // pair-interleaved quantized edge rows
__device__ int   d_srcp[PE];               // pair layout: int2 {off0, off1} (byte offsets)
__device__ uint4 d_epk[PE];                // CSR-permuted packs {src<<7, k01, k23, 0}
__device__ int   d_deg[NN];                // hist; zeroed by epack after scan consumes it
__device__ int   d_degs[NN];               // saved true degree
__device__ int   d_rowptr[NN + 1];         // even-aligned (padded) row starts
__device__ int   d_wp[NN];
__device__ float d_pool[GG * CC];
__device__ float d_cntf[GG];

// ---------------- helpers ------------------------------------------------------
__device__ __forceinline__ float qf(float x) {
    float y = rintf(x * QINV) * QSTEP;
    return fminf(fmaxf(y, QMINV), QMAXV);
}
__device__ __forceinline__ float ex2f(float x) {
    float y;
    asm("ex2.approx.f32 %0, %1;" : "=f"(y) : "f"(x));
    return y;
}

// ---------------- fused: node encoder + degree hist + pool zero -----------------
__global__ void k_pre(const float* __restrict__ x,
                      const float* __restrict__ Wn,
                      const float* __restrict__ bn_,
                      const float* __restrict__ g,
                      const float* __restrict__ b,
                      const float* __restrict__ m,
                      const float* __restrict__ v,
                      const float* __restrict__ eg,
                      const float* __restrict__ eb,
                      const float* __restrict__ em,
                      const float* __restrict__ ev,
                      const float* __restrict__ t,
                      const int* __restrict__ ei) {
    __shared__ float Ws[XDIM * CC];
    __shared__ float bs[CC], As[CC], Ds[CC], Es[CC];
    int tid = threadIdx.x;
    int gi = blockIdx.x * blockDim.x + tid;

    if (tid < XDIM * CC) Ws[tid] = qf(Wn[tid]);
    if (tid < CC) {
        bs[tid] = qf(bn_[tid]);
        float rs = rsqrtf(v[tid] + BN_EPS_F);
        float a = g[tid] * rs;
        As[tid] = a;
        Ds[tid] = b[tid] - m[tid] * a;
        float ga = eg[tid] * rsqrtf(ev[tid] + BN_EPS_F);
        Es[tid] = eb[tid] - em[tid] * ga + GEN_EPS_F;   // D_bne + eps
    }

    if (gi < GG * CC) d_pool[gi] = 0.0f;
    if (gi < EE) atomicAdd(&d_deg[ei[EE + gi]], 1);

    __syncthreads();
    if (gi >= NN) return;

    float tl2 = __ldg(t) * LOG2E_F;           // t[0]
    const float4* xp = (const float4*)(x + gi * XDIM);
    float4 a0 = xp[0], a1 = xp[1];
    float xq[XDIM];
    xq[0] = qf(a0.x); xq[1] = qf(a0.y); xq[2] = qf(a0.z); xq[3] = qf(a0.w);
    xq[4] = qf(a1.x); xq[5] = qf(a1.y); xq[6] = qf(a1.z); xq[7] = qf(a1.w);
    #pragma unroll
    for (int c = 0; c < CC; c++) {
        float acc = bs[c];
        #pragma unroll
        for (int k = 0; k < XDIM; k++) acc = fmaf(xq[k], Ws[k * CC + c], acc);
        float hv = fmaf(As[c], qf(acc), Ds[c]);
        d_h [gi * CC + c] = hv;
        d_hb[gi * CC + c] = (hv + Es[c]) * tl2;
    }
}

// ---------------- scan with even-padding (redundant per-block prefix) -----------
#define SCAN_NB 98
__global__ void k_scan() {
    __shared__ int sh[1024];
    __shared__ int red[32];
    int tid = threadIdx.x;
    int lane = tid & 31, wid = tid >> 5;
    int bid = blockIdx.x;

    // offset = sum of padded deg[0 .. bid*1024)
    int lim = bid * 1024;
    int acc = 0;
    for (int i = tid; i < lim; i += 1024) {
        int d = d_deg[i];
        acc += d + (d & 1);
    }
    #pragma unroll
    for (int o = 16; o > 0; o >>= 1) acc += __shfl_down_sync(0xFFFFFFFF, acc, o);
    if (lane == 0) red[wid] = acc;
    __syncthreads();
    int off;
    {
        int a2 = red[lane];
        #pragma unroll
        for (int o = 16; o > 0; o >>= 1) a2 += __shfl_down_sync(0xFFFFFFFF, a2, o);
        off = __shfl_sync(0xFFFFFFFF, a2, 0);
    }

    int i = bid * 1024 + tid;
    int dv = (i < NN) ? d_deg[i] : 0;
    int vp = dv + (dv & 1);
    sh[tid] = vp;
    __syncthreads();
    for (int o = 1; o < 1024; o <<= 1) {
        int t = (tid >= o) ? sh[tid - o] : 0;
        __syncthreads();
        sh[tid] += t;
        __syncthreads();
    }
    if (i < NN) {
        int r = sh[tid] - vp + off;
        d_rowptr[i] = r;
        d_wp[i] = r;
        d_degs[i] = dv;
        if (i == NN - 1) d_rowptr[NN] = r + vp;
    }
}

// ---------------- phase 1: pack + CSR scatter (+ deg reset) ---------------------
__global__ void k_epack(const float* __restrict__ ea,
                        const int* __restrict__ ei) {
    int e = blockIdx.x * blockDim.x + threadIdx.x;
    if (e < NN) d_deg[e] = 0;                 // reset for next call
    if (e >= EE) return;
    float4 a = ((const float4*)ea)[e];
    int k0 = max(-32768, min(32767, __float2int_rn(a.x * QINV)));
    int k1 = max(-32768, min(32767, __float2int_rn(a.y * QINV)));
    int k2 = max(-32768, min(32767, __float2int_rn(a.z * QINV)));
    int k3 = max(-32768, min(32767, __float2int_rn(a.w * QINV)));
    unsigned y = (unsigned)(k0 & 0xFFFF) | ((unsigned)k1 << 16);
    unsigned z = (unsigned)(k2 & 0xFFFF) | ((unsigned)k3 << 16);
    int src = ei[e];
    int dst = ei[EE + e];
    int pos = atomicAdd(&d_wp[dst], 1);
    __stcs(&d_epk[pos], make_uint4((unsigned)(src << 7), y, z, 0u));  // src*128 bytes
}

// ---------------- phase 2: pair expand (sequential, interleaved rows) ------------
__global__ void k_eexpand(const float* __restrict__ We,
                          const float* __restrict__ be) {
    __shared__ float Ws[EDIM * CC];   // qf(W) * QSTEP (tick-space)
    __shared__ float bs[CC];
    int tid = threadIdx.x;
    if (tid < EDIM * CC) Ws[tid] = qf(We[tid]) * QSTEP;
    if (tid < CC) bs[tid] = qf(be[tid]);
    __syncthreads();
    int pi = blockIdx.x * blockDim.x + tid;
    int npair = d_rowptr[NN] >> 1;
    if (pi >= npair) return;
    uint4 u0 = __ldcs(&d_epk[2 * pi]);
    uint4 u1 = __ldcs(&d_epk[2 * pi + 1]);
    ((int2*)d_srcp)[pi] = make_int2((int)u0.x, (int)u1.x);
    float f0 = (float)(short)(u0.y & 0xFFFF);
    float f1 = (float)(short)(u0.y >> 16);
    float f2 = (float)(short)(u0.z & 0xFFFF);
    float f3 = (float)(short)(u0.z >> 16);
    float g0 = (float)(short)(u1.y & 0xFFFF);
    float g1 = (float)(short)(u1.y >> 16);
    float g2 = (float)(short)(u1.z & 0xFFFF);
    float g3 = (float)(short)(u1.z >> 16);
    unsigned int us[32];
    #pragma unroll
    for (int c = 0; c < CC; c++) {
        float w0 = Ws[0 * CC + c], w1 = Ws[1 * CC + c];
        float w2 = Ws[2 * CC + c], w3 = Ws[3 * CC + c];
        float accA = bs[c], accB = bs[c];
        accA = fmaf(f0, w0, accA); accB = fmaf(g0, w0, accB);
        accA = fmaf(f1, w1, accA); accB = fmaf(g1, w1, accB);
        accA = fmaf(f2, w2, accA); accB = fmaf(g2, w2, accB);
        accA = fmaf(f3, w3, accA); accB = fmaf(g3, w3, accB);
        int kA = max(-32768, min(32767, __float2int_rn(accA * QINV)));
        int kB = max(-32768, min(32767, __float2int_rn(accB * QINV)));
        us[c] = (unsigned)(kA & 0xFFFF) | ((unsigned)kB << 16);
    }
    uint4* o = (uint4*)(d_eq + (size_t)pi * 2 * CC);
    #pragma unroll
    for (int q = 0; q < 8; q++)
        o[q] = make_uint4(us[4 * q], us[4 * q + 1], us[4 * q + 2], us[4 * q + 3]);
}

// ---------------- GENConv softmax aggregation (pair-merged online) ---------------
__global__ void __launch_bounds__(256) k_agg(const float* __restrict__ t, int l,
                      const float* __restrict__ bg, const float* __restrict__ bv) {
    int lane = threadIdx.x & 31;
    int warp = threadIdx.x >> 5;
    int node = blockIdx.x * 8 + warp;
    if (node >= NN) return;

    float tl2  = __ldg(t + l) * LOG2E_F;
    float A2   = QSTEP * __ldg(bg + lane) * rsqrtf(__ldg(bv + lane) + BN_EPS_F) * tl2;
    float eps2 = GEN_EPS_F * tl2;

    int deg = d_degs[node];
    int idx = node * CC + lane;
    if (deg == 0) { d_h2[idx] = d_h[idx]; return; }

    int pair0  = d_rowptr[node] >> 1;
    int npairs = deg >> 1;

    const unsigned* eqw = (const unsigned*)d_eq + (size_t)pair0 * CC + lane;
    const int2*     sp  = (const int2*)d_srcp + pair0;
    const char*     hbl = (const char*)d_hb + lane * 4;

    float mxl = -3.402823466e38f, den = 0.0f, num = 0.0f;

    #pragma unroll 2
    for (int k = 0; k < npairs; ++k) {
        int2     so = __ldcs(sp + k);
        unsigned kk = __ldcs(eqw);
        eqw += CC;
        float hb0 = __ldg((const float*)(hbl + so.x));
        float hb1 = __ldg((const float*)(hbl + so.y));
        float fa  = (float)(short)(kk & 0xFFFF);
        float fb  = (float)(short)(kk >> 16);
        float sl0 = fmaxf(fmaf(fa, A2, hb0), eps2);
        float sl1 = fmaxf(fmaf(fb, A2, hb1), eps2);
        float nm  = fmaxf(mxl, fmaxf(sl0, sl1));
        float ea0 = ex2f(sl0 - nm);
        float ea1 = ex2f(sl1 - nm);
        float ebb = ex2f(mxl - nm);
        den = fmaf(den, ebb, ea0 + ea1);
        num = fmaf(num, ebb, fmaf(ea1, sl1, ea0 * sl0));
        mxl = nm;
    }
    if (deg & 1) {    // last edge sits in slot .x of pair 'npairs'
        int2     so = __ldcs(sp + npairs);
        unsigned kk = __ldcs(eqw);
        float hb0 = __ldg((const float*)(hbl + so.x));
        float fa  = (float)(short)(kk & 0xFFFF);
        float sl0 = fmaxf(fmaf(fa, A2, hb0), eps2);
        float nm  = fmaxf(mxl, sl0);
        float ea0 = ex2f(sl0 - nm);
        float ebb = ex2f(mxl - nm);
        den = fmaf(den, ebb, ea0);
        num = fmaf(num, ebb, ea0 * sl0);
    }
    float agg = num / (fmaxf(den, 1e-16f) * tl2);
    d_h2[idx] = d_h[idx] + agg;
}

// ---------------- per-layer quantized MLP + residual (+ scaled hb emit) ----------
__global__ void __launch_bounds__(128) k_mlp(int l,
        const float* __restrict__ W1, const float* __restrict__ b1,
        const float* __restrict__ g1, const float* __restrict__ bb1,
        const float* __restrict__ m1, const float* __restrict__ v1,
        const float* __restrict__ W2, const float* __restrict__ b2,
        const float* __restrict__ eg, const float* __restrict__ eb,
        const float* __restrict__ em, const float* __restrict__ ev,
        const float* __restrict__ t) {
    __shared__ float w1s[CC * 2 * CC];
    __shared__ float w2s[2 * CC * CC];
    __shared__ float b1s[2 * CC], a1s[2 * CC], d1s[2 * CC], b2s[CC], Es[CC];
    int tid = threadIdx.x;
    const float* W1l = W1 + l * CC * 2 * CC;
    const float* W2l = W2 + l * 2 * CC * CC;
    for (int i = tid; i < CC * 2 * CC; i += 128) {
        w1s[i] = qf(W1l[i]);
        w2s[i] = qf(W2l[i]);
    }
    if (tid < 2 * CC) {
        b1s[tid] = qf(b1[l * 2 * CC + tid]);
        float rsv = rsqrtf(v1[l * 2 * CC + tid] + BN_EPS_F);
        float a = g1[l * 2 * CC + tid] * rsv;
        a1s[tid] = a;
        d1s[tid] = bb1[l * 2 * CC + tid] - m1[l * 2 * CC + tid] * a;
    }
    if (tid < CC) {
        b2s[tid] = qf(b2[l * CC + tid]);
        float ga = eg[tid] * rsqrtf(ev[tid] + BN_EPS_F);
        Es[tid] = eb[tid] - em[tid] * ga + GEN_EPS_F;
    }
    __syncthreads();

    int node = blockIdx.x * 128 + tid;
    if (node >= NN) return;

    float xq[CC];
    const float4* hp = (const float4*)(d_h2 + node * CC);
    #pragma unroll
    for (int i = 0; i < 8; i++) {
        float4 t4 = hp[i];
        xq[4 * i + 0] = qf(t4.x); xq[4 * i + 1] = qf(t4.y);
        xq[4 * i + 2] = qf(t4.z); xq[4 * i + 3] = qf(t4.w);
    }
    float acc2[CC];
    #pragma unroll
    for (int c = 0; c < CC; c++) acc2[c] = b2s[c];

    for (int j = 0; j < 2 * CC; j++) {
        float a = b1s[j];
        #pragma unroll
        for (int k = 0; k < CC; k++) a = fmaf(xq[k], w1s[k * 2 * CC + j], a);
        float z1 = qf(a);
        float zr = qf(fmaxf(fmaf(a1s[j], z1, d1s[j]), 0.0f));
        #pragma unroll
        for (int c = 0; c < CC; c++) acc2[c] = fmaf(zr, w2s[j * CC + c], acc2[c]);
    }
    bool emit_hb = (l < LL - 1);
    float tl2n = emit_hb ? __ldg(t + l + 1) * LOG2E_F : 0.0f;
    const float4* ip = (const float4*)(d_h + node * CC);
    float4* op = (float4*)(d_h + node * CC);
    float4* bp = (float4*)(d_hb + node * CC);
    #pragma unroll
    for (int c = 0; c < CC; c += 4) {
        float4 id4 = ip[c >> 2];
        float4 o;
        o.x = qf(acc2[c + 0]) + id4.x;
        o.y = qf(acc2[c + 1]) + id4.y;
        o.z = qf(acc2[c + 2]) + id4.z;
        o.w = qf(acc2[c + 3]) + id4.w;
        op[c >> 2] = o;
        if (emit_hb) {
            float4 hbv;
            hbv.x = (o.x + Es[c + 0]) * tl2n;
            hbv.y = (o.y + Es[c + 1]) * tl2n;
            hbv.z = (o.z + Es[c + 2]) * tl2n;
            hbv.w = (o.w + Es[c + 3]) * tl2n;
            bp[c >> 2] = hbv;
        }
    }
}

// ---------------- global mean pool ----------------------------------------------
__global__ void k_pool(const int* __restrict__ batch) {
    int lane = threadIdx.x & 31;
    int w = (blockIdx.x * blockDim.x + threadIdx.x) >> 5;
    const int CHUNK = 128;
    int i0 = w * CHUNK;
    if (i0 >= NN) return;
    int i1 = min(i0 + CHUNK, NN);
    int cur = batch[i0];
    float acc = 0.0f;
    for (int i = i0; i < i1; i++) {
        int g = batch[i];
        float val = d_h[i * CC + lane];
        if (g != cur) {
            atomicAdd(&d_pool[cur * CC + lane], acc);
            acc = 0.0f;
            cur = g;
        }
        acc += val;
    }
    atomicAdd(&d_pool[cur * CC + lane], acc);
}

__global__ void k_cnt(const int* __restrict__ batch) {
    int g = blockIdx.x * blockDim.x + threadIdx.x;
    if (g >= GG) return;
    int lo0 = 0, hi0 = NN;
    while (lo0 < hi0) { int mid = (lo0 + hi0) >> 1; if (batch[mid] < g) lo0 = mid + 1; else hi0 = mid; }
    int lo1 = lo0, hi1 = NN;
    while (lo1 < hi1) { int mid = (lo1 + hi1) >> 1; if (batch[mid] < g + 1) lo1 = mid + 1; else hi1 = mid; }
    d_cntf[g] = (float)(lo1 - lo0);
}

__global__ void k_final(const float* __restrict__ Wo, const float* __restrict__ bo,
                        float* __restrict__ out) {
    __shared__ float wq[CC];
    int tid = threadIdx.x;
    if (tid < CC) wq[tid] = qf(Wo[tid]);
    __syncthreads();
    int g = blockIdx.x * blockDim.x + tid;
    if (g >= GG) return;
    float cnt = fmaxf(d_cntf[g], 1.0f);
    float acc = qf(bo[0]);
    #pragma unroll
    for (int c = 0; c < CC; c++) {
        float pm = d_pool[g * CC + c] / cnt;
        acc = fmaf(qf(pm), wq[c], acc);
    }
    float o = qf(acc);
    float s = 1.0f / (1.0f + expf(-o));
    out[g] = qf(s);
}

// ---------------- launch ---------------------------------------------------------
extern "C" void kernel_launch(void* const* d_in, const int* in_sizes, int n_in,
                              void* d_out, int out_size) {
    const float* x    = (const float*)d_in[0];
    const float* ea   = (const float*)d_in[1];
    const float* Wn   = (const float*)d_in[2];
    const float* bn_  = (const float*)d_in[3];
    const float* We   = (const float*)d_in[4];
    const float* be   = (const float*)d_in[5];
    const float* bnng = (const float*)d_in[6];
    const float* bnnb = (const float*)d_in[7];
    const float* bnnm = (const float*)d_in[8];
    const float* bnnv = (const float*)d_in[9];
    const float* bneg = (const float*)d_in[10];
    const float* bneb = (const float*)d_in[11];
    const float* bnem = (const float*)d_in[12];
    const float* bnev = (const float*)d_in[13];
    const float* t    = (const float*)d_in[14];
    const float* W1   = (const float*)d_in[15];
    const float* b1   = (const float*)d_in[16];
    const float* g1   = (const float*)d_in[17];
    const float* bb1  = (const float*)d_in[18];
    const float* m1   = (const float*)d_in[19];
    const float* v1   = (const float*)d_in[20];
    const float* W2   = (const float*)d_in[21];
    const float* b2   = (const float*)d_in[22];
    const float* Wo   = (const float*)d_in[23];
    const float* bo   = (const float*)d_in[24];
    const int*   ei   = (const int*)d_in[25];
    const int*   batch= (const int*)d_in[26];
    float* out = (float*)d_out;

    k_pre<<<(EE + 255) / 256, 256>>>(x, Wn, bn_, bnng, bnnb, bnnm, bnnv,
                                     bneg, bneb, bnem, bnev, t, ei);
    k_scan<<<SCAN_NB, 1024>>>();
    k_epack<<<(EE + 255) / 256, 256>>>(ea, ei);
    k_eexpand<<<(PE / 2 + 255) / 256, 256>>>(We, be);

    for (int l = 0; l < LL; l++) {
        k_agg<<<(NN + 7) / 8, 256>>>(t, l, bneg, bnev);
        k_mlp<<<(NN + 127) / 128, 128>>>(l, W1, b1, g1, bb1, m1, v1, W2, b2,
                                         bneg, bneb, bnem, bnev, t);
    }

    k_pool<<<98, 256>>>(batch);
    k_cnt<<<(GG + 255) / 256, 256>>>(batch);
    k_final<<<(GG + 255) / 256, 256>>>(Wo, bo, out);
}

// round 7
// speedup vs baseline: 1.0950x; 1.0950x over previous
#include <cuda_runtime.h>
#include <cstdint>

#define NN 100000
#define EE 3200000
#define CC 32
#define LL 4
#define GG 512
#define XDIM 8
#define EDIM 4

#define QSTEP 0.0009765625f   // 2^-10
#define QINV  1024.0f
#define QMAXV (32.0f - 0.0009765625f)
#define QMINV (-32.0f)
#define BN_EPS_F 1e-5f
#define GEN_EPS_F 1e-7f
#define LOG2E_F 1.4426950408889634f

// ---------------- scratch (device globals; no allocation allowed) -------------
__device__ float d_h [NN * CC];            // node features
__device__ float d_h2[NN * CC];            // h + agg
__device__ short d_eq[(size_t)EE * CC];    // CSR-permuted quantized edge features
__device__ int   d_srcp[EE];               // CSR-permuted src ids
__device__ int   d_deg[NN];                // zeroed at load; re-zeroed by edge_enc
__device__ int   d_rowptr[NN + 1];
__device__ int   d_wp[NN];
__device__ float d_pool[GG * CC];
__device__ float d_cntf[GG];

// ---------------- helpers ------------------------------------------------------
__device__ __forceinline__ float qf(float x) {
    float y = rintf(x * QINV) * QSTEP;
    return fminf(fmaxf(y, QMINV), QMAXV);
}
__device__ __forceinline__ float ex2f(float x) {
    float y;
    asm("ex2.approx.f32 %0, %1;" : "=f"(y) : "f"(x));
    return y;
}

// ---------------- fused: node encoder + degree hist + pool zero -----------------
__global__ void k_pre(const float* __restrict__ x,
                      const float* __restrict__ Wn,
                      const float* __restrict__ bn_,
                      const float* __restrict__ g,
                      const float* __restrict__ b,
                      const float* __restrict__ m,
                      const float* __restrict__ v,
                      const int* __restrict__ ei) {
    __shared__ float Ws[XDIM * CC];
    __shared__ float bs[CC], As[CC], Ds[CC];
    int tid = threadIdx.x;
    int gi = blockIdx.x * blockDim.x + tid;

    if (tid < XDIM * CC) Ws[tid] = qf(Wn[tid]);
    if (tid < CC) {
        bs[tid] = qf(bn_[tid]);
        float rs = rsqrtf(v[tid] + BN_EPS_F);
        float a = g[tid] * rs;
        As[tid] = a;
        Ds[tid] = b[tid] - m[tid] * a;
    }

    if (gi < GG * CC) d_pool[gi] = 0.0f;
    if (gi < EE) atomicAdd(&d_deg[ei[EE + gi]], 1);

    __syncthreads();
    if (gi >= NN) return;

    const float4* xp = (const float4*)(x + gi * XDIM);
    float4 a0 = xp[0], a1 = xp[1];
    float xq[XDIM];
    xq[0] = qf(a0.x); xq[1] = qf(a0.y); xq[2] = qf(a0.z); xq[3] = qf(a0.w);
    xq[4] = qf(a1.x); xq[5] = qf(a1.y); xq[6] = qf(a1.z); xq[7] = qf(a1.w);
    #pragma unroll
    for (int c = 0; c < CC; c++) {
        float acc = bs[c];
        #pragma unroll
        for (int k = 0; k < XDIM; k++) acc = fmaf(xq[k], Ws[k * CC + c], acc);
        d_h[gi * CC + c] = fmaf(As[c], qf(acc), Ds[c]);
    }
}

// ---------------- single-launch scan (redundant per-block prefix) ---------------
#define SCAN_NB 98
__global__ void k_scan() {
    __shared__ int sh[1024];
    __shared__ int red[32];
    int tid = threadIdx.x;
    int lane = tid & 31, wid = tid >> 5;
    int bid = blockIdx.x;

    int lim = bid * 1024;
    int acc = 0;
    for (int i = tid; i < lim; i += 1024) acc += d_deg[i];
    #pragma unroll
    for (int o = 16; o > 0; o >>= 1) acc += __shfl_down_sync(0xFFFFFFFF, acc, o);
    if (lane == 0) red[wid] = acc;
    __syncthreads();
    int off;
    {
        int a2 = red[lane];
        #pragma unroll
        for (int o = 16; o > 0; o >>= 1) a2 += __shfl_down_sync(0xFFFFFFFF, a2, o);
        off = __shfl_sync(0xFFFFFFFF, a2, 0);
    }

    int i = bid * 1024 + tid;
    int v = (i < NN) ? d_deg[i] : 0;
    sh[tid] = v;
    __syncthreads();
    for (int o = 1; o < 1024; o <<= 1) {
        int t = (tid >= o) ? sh[tid - o] : 0;
        __syncthreads();
        sh[tid] += t;
        __syncthreads();
    }
    if (i < NN) {
        int r = sh[tid] - v + off;
        d_rowptr[i] = r;
        d_wp[i] = r;
    }
    if (bid == 0 && tid == 0) d_rowptr[NN] = EE;
}

// ---------------- edge encoder + CSR scatter (+ deg reset) ----------------------
__global__ void k_edge_enc(const float* __restrict__ ea,
                           const float* __restrict__ We,
                           const float* __restrict__ be,
                           const int* __restrict__ ei) {
    __shared__ float Ws[EDIM * CC];
    __shared__ float bs[CC];
    int tid = threadIdx.x;
    if (tid < EDIM * CC) Ws[tid] = qf(We[tid]);
    if (tid < CC) bs[tid] = qf(be[tid]);
    __syncthreads();
    int e = blockIdx.x * blockDim.x + tid;
    if (e < NN) d_deg[e] = 0;                 // reset for next call
    if (e >= EE) return;
    float4 a = ((const float4*)ea)[e];
    float x0 = qf(a.x), x1 = qf(a.y), x2 = qf(a.z), x3 = qf(a.w);
    unsigned int us[16];
    #pragma unroll
    for (int c = 0; c < CC; c += 2) {
        float acc0 = bs[c], acc1 = bs[c + 1];
        acc0 = fmaf(x0, Ws[0 * CC + c], acc0);
        acc0 = fmaf(x1, Ws[1 * CC + c], acc0);
        acc0 = fmaf(x2, Ws[2 * CC + c], acc0);
        acc0 = fmaf(x3, Ws[3 * CC + c], acc0);
        acc1 = fmaf(x0, Ws[0 * CC + c + 1], acc1);
        acc1 = fmaf(x1, Ws[1 * CC + c + 1], acc1);
        acc1 = fmaf(x2, Ws[2 * CC + c + 1], acc1);
        acc1 = fmaf(x3, Ws[3 * CC + c + 1], acc1);
        int k0 = __float2int_rn(acc0 * QINV);
        int k1 = __float2int_rn(acc1 * QINV);
        k0 = max(-32768, min(32767, k0));
        k1 = max(-32768, min(32767, k1));
        us[c >> 1] = (unsigned)(k0 & 0xFFFF) | ((unsigned)k1 << 16);
    }
    int src = ei[e];
    int dst = ei[EE + e];
    int pos = atomicAdd(&d_wp[dst], 1);
    d_srcp[pos] = src;
    uint4* o = (uint4*)(d_eq + (size_t)pos * CC);
    __stcs(o + 0, make_uint4(us[0],  us[1],  us[2],  us[3]));
    __stcs(o + 1, make_uint4(us[4],  us[5],  us[6],  us[7]));
    __stcs(o + 2, make_uint4(us[8],  us[9],  us[10], us[11]));
    __stcs(o + 3, make_uint4(us[12], us[13], us[14], us[15]));
}

// ---------------- GENConv softmax aggregation (R1-verbatim body) ----------------
__global__ void __launch_bounds__(256) k_agg(const float* __restrict__ t, int l,
                      const float* __restrict__ bg, const float* __restrict__ bb,
                      const float* __restrict__ bm, const float* __restrict__ bv) {
    int lane = threadIdx.x & 31;
    int warp = threadIdx.x >> 5;
    int node = blockIdx.x * 8 + warp;
    if (node >= NN) return;

    float rs = rsqrtf(bv[lane] + BN_EPS_F);
    float ga = bg[lane] * rs;
    float A = QSTEP * ga;                      // e = A*k + D  (BN folded onto int16)
    float D = bb[lane] - bm[lane] * ga;
    float tl2 = t[l] * LOG2E_F;                // log2 domain: one EX2 per edge

    int p0 = d_rowptr[node], p1 = d_rowptr[node + 1];
    float mxl = -3.402823466e38f;
    float den = 0.0f, num = 0.0f;
    const short* eqp = d_eq + (size_t)p0 * CC + lane;

    for (int p = p0; p < p1; ++p) {
        int   src = __ldcs(d_srcp + p);
        short kv  = __ldcs(eqp);
        eqp += CC;
        float hs  = __ldg(d_h + src * CC + lane);
        float ev  = fmaf((float)kv, A, D);
        float m   = fmaxf(hs + ev, 0.0f) + GEN_EPS_F;
        float sl  = m * tl2;
        float dd  = sl - mxl;
        float ex  = ex2f(-fabsf(dd));          // exp2 of the non-max side
        bool  up  = dd > 0.0f;
        float r   = up ? ex : 1.0f;            // rescale old accumulators
        float e1  = up ? 1.0f : ex;            // weight of the new element
        den = fmaf(den, r, e1);
        num = fmaf(num, r, e1 * m);
        mxl = fmaxf(mxl, sl);
    }
    float agg = num / fmaxf(den, 1e-16f);
    int idx = node * CC + lane;
    d_h2[idx] = d_h[idx] + agg;
}

// ---------------- per-layer quantized MLP + residual (R1-verbatim) --------------
__global__ void __launch_bounds__(128) k_mlp(int l,
        const float* __restrict__ W1, const float* __restrict__ b1,
        const float* __restrict__ g1, const float* __restrict__ bb1,
        const float* __restrict__ m1, const float* __restrict__ v1,
        const float* __restrict__ W2, const float* __restrict__ b2) {
    __shared__ float w1s[CC * 2 * CC];   // 32x64
    __shared__ float w2s[2 * CC * CC];   // 64x32
    __shared__ float b1s[2 * CC], a1s[2 * CC], d1s[2 * CC], b2s[CC];
    int tid = threadIdx.x;
    const float* W1l = W1 + l * CC * 2 * CC;
    const float* W2l = W2 + l * 2 * CC * CC;
    for (int i = tid; i < CC * 2 * CC; i += 128) {
        w1s[i] = qf(W1l[i]);
        w2s[i] = qf(W2l[i]);
    }
    if (tid < 2 * CC) {
        b1s[tid] = qf(b1[l * 2 * CC + tid]);
        float rsv = rsqrtf(v1[l * 2 * CC + tid] + BN_EPS_F);
        float a = g1[l * 2 * CC + tid] * rsv;
        a1s[tid] = a;
        d1s[tid] = bb1[l * 2 * CC + tid] - m1[l * 2 * CC + tid] * a;
    }
    if (tid < CC) b2s[tid] = qf(b2[l * CC + tid]);
    __syncthreads();

    int node = blockIdx.x * 128 + tid;
    if (node >= NN) return;

    float xq[CC];
    const float4* hp = (const float4*)(d_h2 + node * CC);
    #pragma unroll
    for (int i = 0; i < 8; i++) {
        float4 t4 = hp[i];
        xq[4 * i + 0] = qf(t4.x); xq[4 * i + 1] = qf(t4.y);
        xq[4 * i + 2] = qf(t4.z); xq[4 * i + 3] = qf(t4.w);
    }
    float acc2[CC];
    #pragma unroll
    for (int c = 0; c < CC; c++) acc2[c] = b2s[c];

    for (int j = 0; j < 2 * CC; j++) {
        float a = b1s[j];
        #pragma unroll
        for (int k = 0; k < CC; k++) a = fmaf(xq[k], w1s[k * 2 * CC + j], a);
        float z1 = qf(a);
        float zr = qf(fmaxf(fmaf(a1s[j], z1, d1s[j]), 0.0f));
        #pragma unroll
        for (int c = 0; c < CC; c++) acc2[c] = fmaf(zr, w2s[j * CC + c], acc2[c]);
    }
    const float4* ip = (const float4*)(d_h + node * CC);
    float4* op = (float4*)(d_h + node * CC);
    #pragma unroll
    for (int c = 0; c < CC; c += 4) {
        float4 id4 = ip[c >> 2];
        float4 o;
        o.x = qf(acc2[c + 0]) + id4.x;
        o.y = qf(acc2[c + 1]) + id4.y;
        o.z = qf(acc2[c + 2]) + id4.z;
        o.w = qf(acc2[c + 3]) + id4.w;
        op[c >> 2] = o;
    }
}

// ---------------- global mean pool ----------------------------------------------
__global__ void k_pool(const int* __restrict__ batch) {
    int lane = threadIdx.x & 31;
    int w = (blockIdx.x * blockDim.x + threadIdx.x) >> 5;
    const int CHUNK = 128;
    int i0 = w * CHUNK;
    if (i0 >= NN) return;
    int i1 = min(i0 + CHUNK, NN);
    int cur = batch[i0];
    float acc = 0.0f;
    for (int i = i0; i < i1; i++) {
        int g = batch[i];
        float val = d_h[i * CC + lane];
        if (g != cur) {
            atomicAdd(&d_pool[cur * CC + lane], acc);
            acc = 0.0f;
            cur = g;
        }
        acc += val;
    }
    atomicAdd(&d_pool[cur * CC + lane], acc);
}

__global__ void k_cnt(const int* __restrict__ batch) {
    int g = blockIdx.x * blockDim.x + threadIdx.x;
    if (g >= GG) return;
    int lo0 = 0, hi0 = NN;
    while (lo0 < hi0) { int mid = (lo0 + hi0) >> 1; if (batch[mid] < g) lo0 = mid + 1; else hi0 = mid; }
    int lo1 = lo0, hi1 = NN;
    while (lo1 < hi1) { int mid = (lo1 + hi1) >> 1; if (batch[mid] < g + 1) lo1 = mid + 1; else hi1 = mid; }
    d_cntf[g] = (float)(lo1 - lo0);
}

__global__ void k_final(const float* __restrict__ Wo, const float* __restrict__ bo,
                        float* __restrict__ out) {
    __shared__ float wq[CC];
    int tid = threadIdx.x;
    if (tid < CC) wq[tid] = qf(Wo[tid]);
    __syncthreads();
    int g = blockIdx.x * blockDim.x + tid;
    if (g >= GG) return;
    float cnt = fmaxf(d_cntf[g], 1.0f);
    float acc = qf(bo[0]);
    #pragma unroll
    for (int c = 0; c < CC; c++) {
        float pm = d_pool[g * CC + c] / cnt;
        acc = fmaf(qf(pm), wq[c], acc);
    }
    float o = qf(acc);
    float s = 1.0f / (1.0f + expf(-o));
    out[g] = qf(s);
}

// ---------------- launch ---------------------------------------------------------
extern "C" void kernel_launch(void* const* d_in, const int* in_sizes, int n_in,
                              void* d_out, int out_size) {
    const float* x    = (const float*)d_in[0];
    const float* ea   = (const float*)d_in[1];
    const float* Wn   = (const float*)d_in[2];
    const float* bn_  = (const float*)d_in[3];
    const float* We   = (const float*)d_in[4];
    const float* be   = (const float*)d_in[5];
    const float* bnng = (const float*)d_in[6];
    const float* bnnb = (const float*)d_in[7];
    const float* bnnm = (const float*)d_in[8];
    const float* bnnv = (const float*)d_in[9];
    const float* bneg = (const float*)d_in[10];
    const float* bneb = (const float*)d_in[11];
    const float* bnem = (const float*)d_in[12];
    const float* bnev = (const float*)d_in[13];
    const float* t    = (const float*)d_in[14];
    const float* W1   = (const float*)d_in[15];
    const float* b1   = (const float*)d_in[16];
    const float* g1   = (const float*)d_in[17];
    const float* bb1  = (const float*)d_in[18];
    const float* m1   = (const float*)d_in[19];
    const float* v1   = (const float*)d_in[20];
    const float* W2   = (const float*)d_in[21];
    const float* b2   = (const float*)d_in[22];
    const float* Wo   = (const float*)d_in[23];
    const float* bo   = (const float*)d_in[24];
    const int*   ei   = (const int*)d_in[25];
    const int*   batch= (const int*)d_in[26];
    float* out = (float*)d_out;

    k_pre<<<(EE + 255) / 256, 256>>>(x, Wn, bn_, bnng, bnnb, bnnm, bnnv, ei);
    k_scan<<<SCAN_NB, 1024>>>();
    k_edge_enc<<<(EE + 255) / 256, 256>>>(ea, We, be, ei);

    for (int l = 0; l < LL; l++) {
        k_agg<<<(NN + 7) / 8, 256>>>(t, l, bneg, bneb, bnem, bnev);
        k_mlp<<<(NN + 127) / 128, 128>>>(l, W1, b1, g1, bb1, m1, v1, W2, b2);
    }

    k_pool<<<98, 256>>>(batch);
    k_cnt<<<(GG + 255) / 256, 256>>>(batch);
    k_final<<<(GG + 255) / 256, 256>>>(Wo, bo, out);
}

// round 8
// speedup vs baseline: 1.1117x; 1.0152x over previous
#include <cuda_runtime.h>
#include <cstdint>

#define NN 100000
#define EE 3200000
#define CC 32
#define LL 4
#define GG 512
#define XDIM 8
#define EDIM 4

#define QSTEP 0.0009765625f   // 2^-10
#define QINV  1024.0f
#define QMAXV (32.0f - 0.0009765625f)
#define QMINV (-32.0f)
#define BN_EPS_F 1e-5f
#define GEN_EPS_F 1e-7f
#define LOG2E_F 1.4426950408889634f

// ---------------- scratch (device globals; no allocation allowed) -------------
__device__ float d_h [NN * CC];            // node features
__device__ float d_hb[NN * CC];            // (h + D_bne + eps) * t[l]*log2e
__device__ float d_h2[NN * CC];            // h + agg
__device__ short d_eq[(size_t)EE * CC];    // CSR-permuted quantized edge features
__device__ int   d_srcp[EE];               // CSR-permuted src byte-offsets (src*128)
__device__ int   d_deg[NN];                // zeroed at load; re-zeroed by edge_enc
__device__ int   d_rowptr[NN + 1];
__device__ int   d_wp[NN];
__device__ float d_pool[GG * CC];
__device__ float d_cntf[GG];

// ---------------- helpers ------------------------------------------------------
__device__ __forceinline__ float qf(float x) {
    float y = rintf(x * QINV) * QSTEP;
    return fminf(fmaxf(y, QMINV), QMAXV);
}
__device__ __forceinline__ float ex2f(float x) {
    float y;
    asm("ex2.approx.f32 %0, %1;" : "=f"(y) : "f"(x));
    return y;
}

// ---------------- fused: node encoder + degree hist + pool zero -----------------
__global__ void k_pre(const float* __restrict__ x,
                      const float* __restrict__ Wn,
                      const float* __restrict__ bn_,
                      const float* __restrict__ g,
                      const float* __restrict__ b,
                      const float* __restrict__ m,
                      const float* __restrict__ v,
                      const float* __restrict__ eg,
                      const float* __restrict__ eb,
                      const float* __restrict__ em,
                      const float* __restrict__ ev,
                      const float* __restrict__ t,
                      const int* __restrict__ ei) {
    __shared__ float Ws[XDIM * CC];
    __shared__ float bs[CC], As[CC], Ds[CC], Es[CC];
    int tid = threadIdx.x;
    int gi = blockIdx.x * blockDim.x + tid;

    if (tid < XDIM * CC) Ws[tid] = qf(Wn[tid]);
    if (tid < CC) {
        bs[tid] = qf(bn_[tid]);
        float rs = rsqrtf(v[tid] + BN_EPS_F);
        float a = g[tid] * rs;
        As[tid] = a;
        Ds[tid] = b[tid] - m[tid] * a;
        float ga = eg[tid] * rsqrtf(ev[tid] + BN_EPS_F);
        Es[tid] = eb[tid] - em[tid] * ga + GEN_EPS_F;   // D_bne + eps
    }

    if (gi < GG * CC) d_pool[gi] = 0.0f;
    if (gi < EE) atomicAdd(&d_deg[ei[EE + gi]], 1);

    __syncthreads();
    if (gi >= NN) return;

    float tl2 = __ldg(t) * LOG2E_F;           // t[0]
    const float4* xp = (const float4*)(x + gi * XDIM);
    float4 a0 = xp[0], a1 = xp[1];
    float xq[XDIM];
    xq[0] = qf(a0.x); xq[1] = qf(a0.y); xq[2] = qf(a0.z); xq[3] = qf(a0.w);
    xq[4] = qf(a1.x); xq[5] = qf(a1.y); xq[6] = qf(a1.z); xq[7] = qf(a1.w);
    #pragma unroll
    for (int c = 0; c < CC; c++) {
        float acc = bs[c];
        #pragma unroll
        for (int k = 0; k < XDIM; k++) acc = fmaf(xq[k], Ws[k * CC + c], acc);
        float hv = fmaf(As[c], qf(acc), Ds[c]);
        d_h [gi * CC + c] = hv;
        d_hb[gi * CC + c] = (hv + Es[c]) * tl2;
    }
}

// ---------------- single-launch scan (redundant per-block prefix) ---------------
#define SCAN_NB 98
__global__ void k_scan() {
    __shared__ int sh[1024];
    __shared__ int red[32];
    int tid = threadIdx.x;
    int lane = tid & 31, wid = tid >> 5;
    int bid = blockIdx.x;

    int lim = bid * 1024;
    int acc = 0;
    for (int i = tid; i < lim; i += 1024) acc += d_deg[i];
    #pragma unroll
    for (int o = 16; o > 0; o >>= 1) acc += __shfl_down_sync(0xFFFFFFFF, acc, o);
    if (lane == 0) red[wid] = acc;
    __syncthreads();
    int off;
    {
        int a2 = red[lane];
        #pragma unroll
        for (int o = 16; o > 0; o >>= 1) a2 += __shfl_down_sync(0xFFFFFFFF, a2, o);
        off = __shfl_sync(0xFFFFFFFF, a2, 0);
    }

    int i = bid * 1024 + tid;
    int v = (i < NN) ? d_deg[i] : 0;
    sh[tid] = v;
    __syncthreads();
    for (int o = 1; o < 1024; o <<= 1) {
        int t = (tid >= o) ? sh[tid - o] : 0;
        __syncthreads();
        sh[tid] += t;
        __syncthreads();
    }
    if (i < NN) {
        int r = sh[tid] - v + off;
        d_rowptr[i] = r;
        d_wp[i] = r;
    }
    if (bid == 0 && tid == 0) d_rowptr[NN] = EE;
}

// ---------------- edge encoder + CSR scatter (+ deg reset) ----------------------
__global__ void k_edge_enc(const float* __restrict__ ea,
                           const float* __restrict__ We,
                           const float* __restrict__ be,
                           const int* __restrict__ ei) {
    __shared__ float Ws[EDIM * CC];
    __shared__ float bs[CC];
    int tid = threadIdx.x;
    if (tid < EDIM * CC) Ws[tid] = qf(We[tid]);
    if (tid < CC) bs[tid] = qf(be[tid]);
    __syncthreads();
    int e = blockIdx.x * blockDim.x + tid;
    if (e < NN) d_deg[e] = 0;                 // reset for next call
    if (e >= EE) return;
    float4 a = ((const float4*)ea)[e];
    float x0 = qf(a.x), x1 = qf(a.y), x2 = qf(a.z), x3 = qf(a.w);
    unsigned int us[16];
    #pragma unroll
    for (int c = 0; c < CC; c += 2) {
        float acc0 = bs[c], acc1 = bs[c + 1];
        acc0 = fmaf(x0, Ws[0 * CC + c], acc0);
        acc0 = fmaf(x1, Ws[1 * CC + c], acc0);
        acc0 = fmaf(x2, Ws[2 * CC + c], acc0);
        acc0 = fmaf(x3, Ws[3 * CC + c], acc0);
        acc1 = fmaf(x0, Ws[0 * CC + c + 1], acc1);
        acc1 = fmaf(x1, Ws[1 * CC + c + 1], acc1);
        acc1 = fmaf(x2, Ws[2 * CC + c + 1], acc1);
        acc1 = fmaf(x3, Ws[3 * CC + c + 1], acc1);
        int k0 = __float2int_rn(acc0 * QINV);
        int k1 = __float2int_rn(acc1 * QINV);
        k0 = max(-32768, min(32767, k0));
        k1 = max(-32768, min(32767, k1));
        us[c >> 1] = (unsigned)(k0 & 0xFFFF) | ((unsigned)k1 << 16);
    }
    int src = ei[e];
    int dst = ei[EE + e];
    int pos = atomicAdd(&d_wp[dst], 1);
    d_srcp[pos] = src << 7;                   // byte offset: src * CC * 4
    uint4* o = (uint4*)(d_eq + (size_t)pos * CC);
    __stcs(o + 0, make_uint4(us[0],  us[1],  us[2],  us[3]));
    __stcs(o + 1, make_uint4(us[4],  us[5],  us[6],  us[7]));
    __stcs(o + 2, make_uint4(us[8],  us[9],  us[10], us[11]));
    __stcs(o + 3, make_uint4(us[12], us[13], us[14], us[15]));
}

// ---------------- GENConv softmax aggregation (max-free, 1 ex2/edge) ------------
__global__ void __launch_bounds__(256) k_agg(const float* __restrict__ t, int l,
                      const float* __restrict__ bg, const float* __restrict__ bv) {
    int lane = threadIdx.x & 31;
    int warp = threadIdx.x >> 5;
    int node = blockIdx.x * 8 + warp;
    if (node >= NN) return;

    float tl2  = __ldg(t + l) * LOG2E_F;
    float A2   = QSTEP * __ldg(bg + lane) * rsqrtf(__ldg(bv + lane) + BN_EPS_F) * tl2;
    float eps2 = GEN_EPS_F * tl2;

    int p0 = d_rowptr[node], p1 = d_rowptr[node + 1];
    const short* eqp = d_eq + (size_t)p0 * CC + lane;
    const char*  hbl = (const char*)d_hb + lane * 4;

    float den = 0.0f, num = 0.0f;
    for (int p = p0; p < p1; ++p) {
        int   off = __ldcs(d_srcp + p);
        short kv  = __ldcs(eqp);
        eqp += CC;
        float hbv = __ldg((const float*)(hbl + off));   // pre-scaled by tl2
        float sl  = fmaxf(fmaf((float)kv, A2, hbv), eps2);
        float e   = ex2f(sl);
        den += e;
        num = fmaf(e, sl, num);
    }
    float agg = num / (fmaxf(den, 1e-16f) * tl2);
    int idx = node * CC + lane;
    d_h2[idx] = d_h[idx] + agg;
}

// ---------------- per-layer quantized MLP + residual (+ scaled hb emit) ----------
__global__ void __launch_bounds__(128) k_mlp(int l,
        const float* __restrict__ W1, const float* __restrict__ b1,
        const float* __restrict__ g1, const float* __restrict__ bb1,
        const float* __restrict__ m1, const float* __restrict__ v1,
        const float* __restrict__ W2, const float* __restrict__ b2,
        const float* __restrict__ eg, const float* __restrict__ eb,
        const float* __restrict__ em, const float* __restrict__ ev,
        const float* __restrict__ t) {
    __shared__ float w1s[CC * 2 * CC];
    __shared__ float w2s[2 * CC * CC];
    __shared__ float b1s[2 * CC], a1s[2 * CC], d1s[2 * CC], b2s[CC], Es[CC];
    int tid = threadIdx.x;
    const float* W1l = W1 + l * CC * 2 * CC;
    const float* W2l = W2 + l * 2 * CC * CC;
    for (int i = tid; i < CC * 2 * CC; i += 128) {
        w1s[i] = qf(W1l[i]);
        w2s[i] = qf(W2l[i]);
    }
    if (tid < 2 * CC) {
        b1s[tid] = qf(b1[l * 2 * CC + tid]);
        float rsv = rsqrtf(v1[l * 2 * CC + tid] + BN_EPS_F);
        float a = g1[l * 2 * CC + tid] * rsv;
        a1s[tid] = a;
        d1s[tid] = bb1[l * 2 * CC + tid] - m1[l * 2 * CC + tid] * a;
    }
    if (tid < CC) {
        b2s[tid] = qf(b2[l * CC + tid]);
        float ga = eg[tid] * rsqrtf(ev[tid] + BN_EPS_F);
        Es[tid] = eb[tid] - em[tid] * ga + GEN_EPS_F;
    }
    __syncthreads();

    int node = blockIdx.x * 128 + tid;
    if (node >= NN) return;

    float xq[CC];
    const float4* hp = (const float4*)(d_h2 + node * CC);
    #pragma unroll
    for (int i = 0; i < 8; i++) {
        float4 t4 = hp[i];
        xq[4 * i + 0] = qf(t4.x); xq[4 * i + 1] = qf(t4.y);
        xq[4 * i + 2] = qf(t4.z); xq[4 * i + 3] = qf(t4.w);
    }
    float acc2[CC];
    #pragma unroll
    for (int c = 0; c < CC; c++) acc2[c] = b2s[c];

    for (int j = 0; j < 2 * CC; j++) {
        float a = b1s[j];
        #pragma unroll
        for (int k = 0; k < CC; k++) a = fmaf(xq[k], w1s[k * 2 * CC + j], a);
        float z1 = qf(a);
        float zr = qf(fmaxf(fmaf(a1s[j], z1, d1s[j]), 0.0f));
        #pragma unroll
        for (int c = 0; c < CC; c++) acc2[c] = fmaf(zr, w2s[j * CC + c], acc2[c]);
    }
    bool emit_hb = (l < LL - 1);
    float tl2n = emit_hb ? __ldg(t + l + 1) * LOG2E_F : 0.0f;
    const float4* ip = (const float4*)(d_h + node * CC);
    float4* op = (float4*)(d_h + node * CC);
    float4* bp = (float4*)(d_hb + node * CC);
    #pragma unroll
    for (int c = 0; c < CC; c += 4) {
        float4 id4 = ip[c >> 2];
        float4 o;
        o.x = qf(acc2[c + 0]) + id4.x;
        o.y = qf(acc2[c + 1]) + id4.y;
        o.z = qf(acc2[c + 2]) + id4.z;
        o.w = qf(acc2[c + 3]) + id4.w;
        op[c >> 2] = o;
        if (emit_hb) {
            float4 hbv;
            hbv.x = (o.x + Es[c + 0]) * tl2n;
            hbv.y = (o.y + Es[c + 1]) * tl2n;
            hbv.z = (o.z + Es[c + 2]) * tl2n;
            hbv.w = (o.w + Es[c + 3]) * tl2n;
            bp[c >> 2] = hbv;
        }
    }
}

// ---------------- global mean pool ----------------------------------------------
__global__ void k_pool(const int* __restrict__ batch) {
    int lane = threadIdx.x & 31;
    int w = (blockIdx.x * blockDim.x + threadIdx.x) >> 5;
    const int CHUNK = 128;
    int i0 = w * CHUNK;
    if (i0 >= NN) return;
    int i1 = min(i0 + CHUNK, NN);
    int cur = batch[i0];
    float acc = 0.0f;
    for (int i = i0; i < i1; i++) {
        int g = batch[i];
        float val = d_h[i * CC + lane];
        if (g != cur) {
            atomicAdd(&d_pool[cur * CC + lane], acc);
            acc = 0.0f;
            cur = g;
        }
        acc += val;
    }
    atomicAdd(&d_pool[cur * CC + lane], acc);
}

__global__ void k_cnt(const int* __restrict__ batch) {
    int g = blockIdx.x * blockDim.x + threadIdx.x;
    if (g >= GG) return;
    int lo0 = 0, hi0 = NN;
    while (lo0 < hi0) { int mid = (lo0 + hi0) >> 1; if (batch[mid] < g) lo0 = mid + 1; else hi0 = mid; }
    int lo1 = lo0, hi1 = NN;
    while (lo1 < hi1) { int mid = (lo1 + hi1) >> 1; if (batch[mid] < g + 1) lo1 = mid + 1; else hi1 = mid; }
    d_cntf[g] = (float)(lo1 - lo0);
}

__global__ void k_final(const float* __restrict__ Wo, const float* __restrict__ bo,
                        float* __restrict__ out) {
    __shared__ float wq[CC];
    int tid = threadIdx.x;
    if (tid < CC) wq[tid] = qf(Wo[tid]);
    __syncthreads();
    int g = blockIdx.x * blockDim.x + tid;
    if (g >= GG) return;
    float cnt = fmaxf(d_cntf[g], 1.0f);
    float acc = qf(bo[0]);
    #pragma unroll
    for (int c = 0; c < CC; c++) {
        float pm = d_pool[g * CC + c] / cnt;
        acc = fmaf(qf(pm), wq[c], acc);
    }
    float o = qf(acc);
    float s = 1.0f / (1.0f + expf(-o));
    out[g] = qf(s);
}

// ---------------- launch ---------------------------------------------------------
extern "C" void kernel_launch(void* const* d_in, const int* in_sizes, int n_in,
                              void* d_out, int out_size) {
    const float* x    = (const float*)d_in[0];
    const float* ea   = (const float*)d_in[1];
    const float* Wn   = (const float*)d_in[2];
    const float* bn_  = (const float*)d_in[3];
    const float* We   = (const float*)d_in[4];
    const float* be   = (const float*)d_in[5];
    const float* bnng = (const float*)d_in[6];
    const float* bnnb = (const float*)d_in[7];
    const float* bnnm = (const float*)d_in[8];
    const float* bnnv = (const float*)d_in[9];
    const float* bneg = (const float*)d_in[10];
    const float* bneb = (const float*)d_in[11];
    const float* bnem = (const float*)d_in[12];
    const float* bnev = (const float*)d_in[13];
    const float* t    = (const float*)d_in[14];
    const float* W1   = (const float*)d_in[15];
    const float* b1   = (const float*)d_in[16];
    const float* g1   = (const float*)d_in[17];
    const float* bb1  = (const float*)d_in[18];
    const float* m1   = (const float*)d_in[19];
    const float* v1   = (const float*)d_in[20];
    const float* W2   = (const float*)d_in[21];
    const float* b2   = (const float*)d_in[22];
    const float* Wo   = (const float*)d_in[23];
    const float* bo   = (const float*)d_in[24];
    const int*   ei   = (const int*)d_in[25];
    const int*   batch= (const int*)d_in[26];
    float* out = (float*)d_out;

    k_pre<<<(EE + 255) / 256, 256>>>(x, Wn, bn_, bnng, bnnb, bnnm, bnnv,
                                     bneg, bneb, bnem, bnev, t, ei);
    k_scan<<<SCAN_NB, 1024>>>();
    k_edge_enc<<<(EE + 255) / 256, 256>>>(ea, We, be, ei);

    for (int l = 0; l < LL; l++) {
        k_agg<<<(NN + 7) / 8, 256>>>(t, l, bneg, bnev);
        k_mlp<<<(NN + 127) / 128, 128>>>(l, W1, b1, g1, bb1, m1, v1, W2, b2,
                                         bneg, bneb, bnem, bnev, t);
    }

    k_pool<<<98, 256>>>(batch);
    k_cnt<<<(GG + 255) / 256, 256>>>(batch);
    k_final<<<(GG + 255) / 256, 256>>>(Wo, bo, out);
}

// round 9
// speedup vs baseline: 1.1417x; 1.0270x over previous
#include <cuda_runtime.h>
#include <cstdint>

#define NN 100000
#define EE 3200000
#define CC 32
#define LL 4
#define GG 512
#define XDIM 8
#define EDIM 4

#define QSTEP 0.0009765625f   // 2^-10
#define QINV  1024.0f
#define QMAXV (32.0f - 0.0009765625f)
#define QMINV (-32.0f)
#define BN_EPS_F 1e-5f
#define GEN_EPS_F 1e-7f
#define LOG2E_F 1.4426950408889634f

// ---------------- scratch (device globals; no allocation allowed) -------------
__device__ float d_h [NN * CC];            // node features
__device__ float d_hb[NN * CC];            // (h + D_bne + eps) * t[l]*log2e
__device__ float d_h2[NN * CC];            // h + agg
__device__ short d_eq[(size_t)EE * CC];    // CSR-permuted quantized edge features
__device__ int   d_srcp[EE];               // CSR-permuted src byte-offsets (src*128)
__device__ int   d_deg[NN];                // zeroed at load; re-zeroed by edge_enc
__device__ int   d_rowptr[NN + 1];
__device__ int   d_wp[NN];
__device__ float d_pool[GG * CC];
__device__ float d_cntf[GG];

// ---------------- helpers ------------------------------------------------------
__device__ __forceinline__ float qf(float x) {
    float y = rintf(x * QINV) * QSTEP;
    return fminf(fmaxf(y, QMINV), QMAXV);
}
__device__ __forceinline__ float ex2f(float x) {
    float y;
    asm("ex2.approx.f32 %0, %1;" : "=f"(y) : "f"(x));
    return y;
}

// ---------------- fused: node encoder + degree hist + pool zero -----------------
__global__ void k_pre(const float* __restrict__ x,
                      const float* __restrict__ Wn,
                      const float* __restrict__ bn_,
                      const float* __restrict__ g,
                      const float* __restrict__ b,
                      const float* __restrict__ m,
                      const float* __restrict__ v,
                      const float* __restrict__ eg,
                      const float* __restrict__ eb,
                      const float* __restrict__ em,
                      const float* __restrict__ ev,
                      const float* __restrict__ t,
                      const int* __restrict__ ei) {
    __shared__ float Ws[XDIM * CC];
    __shared__ float bs[CC], As[CC], Ds[CC], Es[CC];
    int tid = threadIdx.x;
    int gi = blockIdx.x * blockDim.x + tid;

    if (tid < XDIM * CC) Ws[tid] = qf(Wn[tid]);
    if (tid < CC) {
        bs[tid] = qf(bn_[tid]);
        float rs = rsqrtf(v[tid] + BN_EPS_F);
        float a = g[tid] * rs;
        As[tid] = a;
        Ds[tid] = b[tid] - m[tid] * a;
        float ga = eg[tid] * rsqrtf(ev[tid] + BN_EPS_F);
        Es[tid] = eb[tid] - em[tid] * ga + GEN_EPS_F;   // D_bne + eps
    }

    if (gi < GG * CC) d_pool[gi] = 0.0f;
    if (gi < EE) atomicAdd(&d_deg[ei[EE + gi]], 1);

    __syncthreads();
    if (gi >= NN) return;

    float tl2 = __ldg(t) * LOG2E_F;           // t[0]
    const float4* xp = (const float4*)(x + gi * XDIM);
    float4 a0 = xp[0], a1 = xp[1];
    float xq[XDIM];
    xq[0] = qf(a0.x); xq[1] = qf(a0.y); xq[2] = qf(a0.z); xq[3] = qf(a0.w);
    xq[4] = qf(a1.x); xq[5] = qf(a1.y); xq[6] = qf(a1.z); xq[7] = qf(a1.w);
    #pragma unroll
    for (int c = 0; c < CC; c++) {
        float acc = bs[c];
        #pragma unroll
        for (int k = 0; k < XDIM; k++) acc = fmaf(xq[k], Ws[k * CC + c], acc);
        float hv = fmaf(As[c], qf(acc), Ds[c]);
        d_h [gi * CC + c] = hv;
        d_hb[gi * CC + c] = (hv + Es[c]) * tl2;
    }
}

// ---------------- single-launch scan (redundant per-block prefix) ---------------
#define SCAN_NB 98
__global__ void k_scan() {
    __shared__ int sh[1024];
    __shared__ int red[32];
    int tid = threadIdx.x;
    int lane = tid & 31, wid = tid >> 5;
    int bid = blockIdx.x;

    int lim = bid * 1024;
    int acc = 0;
    for (int i = tid; i < lim; i += 1024) acc += d_deg[i];
    #pragma unroll
    for (int o = 16; o > 0; o >>= 1) acc += __shfl_down_sync(0xFFFFFFFF, acc, o);
    if (lane == 0) red[wid] = acc;
    __syncthreads();
    int off;
    {
        int a2 = red[lane];
        #pragma unroll
        for (int o = 16; o > 0; o >>= 1) a2 += __shfl_down_sync(0xFFFFFFFF, a2, o);
        off = __shfl_sync(0xFFFFFFFF, a2, 0);
    }

    int i = bid * 1024 + tid;
    int v = (i < NN) ? d_deg[i] : 0;
    sh[tid] = v;
    __syncthreads();
    for (int o = 1; o < 1024; o <<= 1) {
        int t = (tid >= o) ? sh[tid - o] : 0;
        __syncthreads();
        sh[tid] += t;
        __syncthreads();
    }
    if (i < NN) {
        int r = sh[tid] - v + off;
        d_rowptr[i] = r;
        d_wp[i] = r;
    }
    if (bid == 0 && tid == 0) d_rowptr[NN] = EE;
}

// ---------------- edge encoder + CSR scatter (+ deg reset) ----------------------
__global__ void k_edge_enc(const float* __restrict__ ea,
                           const float* __restrict__ We,
                           const float* __restrict__ be,
                           const int* __restrict__ ei) {
    __shared__ float Ws[EDIM * CC];
    __shared__ float bs[CC];
    int tid = threadIdx.x;
    if (tid < EDIM * CC) Ws[tid] = qf(We[tid]);
    if (tid < CC) bs[tid] = qf(be[tid]);
    __syncthreads();
    int e = blockIdx.x * blockDim.x + tid;
    if (e < NN) d_deg[e] = 0;                 // reset for next call
    if (e >= EE) return;
    float4 a = ((const float4*)ea)[e];
    float x0 = qf(a.x), x1 = qf(a.y), x2 = qf(a.z), x3 = qf(a.w);
    unsigned int us[16];
    #pragma unroll
    for (int c = 0; c < CC; c += 2) {
        float acc0 = bs[c], acc1 = bs[c + 1];
        acc0 = fmaf(x0, Ws[0 * CC + c], acc0);
        acc0 = fmaf(x1, Ws[1 * CC + c], acc0);
        acc0 = fmaf(x2, Ws[2 * CC + c], acc0);
        acc0 = fmaf(x3, Ws[3 * CC + c], acc0);
        acc1 = fmaf(x0, Ws[0 * CC + c + 1], acc1);
        acc1 = fmaf(x1, Ws[1 * CC + c + 1], acc1);
        acc1 = fmaf(x2, Ws[2 * CC + c + 1], acc1);
        acc1 = fmaf(x3, Ws[3 * CC + c + 1], acc1);
        int k0 = __float2int_rn(acc0 * QINV);
        int k1 = __float2int_rn(acc1 * QINV);
        k0 = max(-32768, min(32767, k0));
        k1 = max(-32768, min(32767, k1));
        us[c >> 1] = (unsigned)(k0 & 0xFFFF) | ((unsigned)k1 << 16);
    }
    int src = ei[e];
    int dst = ei[EE + e];
    int pos = atomicAdd(&d_wp[dst], 1);
    d_srcp[pos] = src << 7;                   // byte offset: src * CC * 4
    uint4* o = (uint4*)(d_eq + (size_t)pos * CC);
    __stcs(o + 0, make_uint4(us[0],  us[1],  us[2],  us[3]));
    __stcs(o + 1, make_uint4(us[4],  us[5],  us[6],  us[7]));
    __stcs(o + 2, make_uint4(us[8],  us[9],  us[10], us[11]));
    __stcs(o + 3, make_uint4(us[12], us[13], us[14], us[15]));
}

// ---------------- GENConv softmax aggregation (max-free, KB=4 batched) ----------
__global__ void __launch_bounds__(256) k_agg(const float* __restrict__ t, int l,
                      const float* __restrict__ bg, const float* __restrict__ bv) {
    int lane = threadIdx.x & 31;
    int warp = threadIdx.x >> 5;
    int node = blockIdx.x * 8 + warp;
    if (node >= NN) return;

    float tl2  = __ldg(t + l) * LOG2E_F;
    float A2   = QSTEP * __ldg(bg + lane) * rsqrtf(__ldg(bv + lane) + BN_EPS_F) * tl2;
    float eps2 = GEN_EPS_F * tl2;

    int p0 = d_rowptr[node], p1 = d_rowptr[node + 1];
    const short* eqp = d_eq + (size_t)p0 * CC + lane;
    const char*  hbl = (const char*)d_hb + lane * 4;
    const int*   sp  = d_srcp + p0;

    float den = 0.0f, num = 0.0f;
    int n = p1 - p0;
    int nfull = n & ~3;

    for (int k = 0; k < nfull; k += 4) {
        int o0 = __ldcs(sp + k + 0);
        int o1 = __ldcs(sp + k + 1);
        int o2 = __ldcs(sp + k + 2);
        int o3 = __ldcs(sp + k + 3);
        short q0 = __ldcs(eqp + 0 * CC);
        short q1 = __ldcs(eqp + 1 * CC);
        short q2 = __ldcs(eqp + 2 * CC);
        short q3 = __ldcs(eqp + 3 * CC);
        eqp += 4 * CC;
        float h0 = __ldg((const float*)(hbl + o0));
        float h1 = __ldg((const float*)(hbl + o1));
        float h2 = __ldg((const float*)(hbl + o2));
        float h3 = __ldg((const float*)(hbl + o3));
        float s0 = fmaxf(fmaf((float)q0, A2, h0), eps2);
        float s1 = fmaxf(fmaf((float)q1, A2, h1), eps2);
        float s2 = fmaxf(fmaf((float)q2, A2, h2), eps2);
        float s3 = fmaxf(fmaf((float)q3, A2, h3), eps2);
        float e0 = ex2f(s0);
        float e1 = ex2f(s1);
        float e2 = ex2f(s2);
        float e3 = ex2f(s3);
        den += (e0 + e1) + (e2 + e3);
        num = fmaf(e0, s0, num);
        num = fmaf(e1, s1, num);
        num = fmaf(e2, s2, num);
        num = fmaf(e3, s3, num);
    }
    for (int k = nfull; k < n; ++k) {
        int   off = __ldcs(sp + k);
        short kv  = __ldcs(eqp);
        eqp += CC;
        float hbv = __ldg((const float*)(hbl + off));
        float sl  = fmaxf(fmaf((float)kv, A2, hbv), eps2);
        float e   = ex2f(sl);
        den += e;
        num = fmaf(e, sl, num);
    }
    float agg = num / (fmaxf(den, 1e-16f) * tl2);
    int idx = node * CC + lane;
    d_h2[idx] = d_h[idx] + agg;
}

// ---------------- per-layer quantized MLP + residual (+ scaled hb emit) ----------
__global__ void __launch_bounds__(128) k_mlp(int l,
        const float* __restrict__ W1, const float* __restrict__ b1,
        const float* __restrict__ g1, const float* __restrict__ bb1,
        const float* __restrict__ m1, const float* __restrict__ v1,
        const float* __restrict__ W2, const float* __restrict__ b2,
        const float* __restrict__ eg, const float* __restrict__ eb,
        const float* __restrict__ em, const float* __restrict__ ev,
        const float* __restrict__ t) {
    __shared__ float w1s[CC * 2 * CC];
    __shared__ float w2s[2 * CC * CC];
    __shared__ float b1s[2 * CC], a1s[2 * CC], d1s[2 * CC], b2s[CC], Es[CC];
    int tid = threadIdx.x;
    const float* W1l = W1 + l * CC * 2 * CC;
    const float* W2l = W2 + l * 2 * CC * CC;
    for (int i = tid; i < CC * 2 * CC; i += 128) {
        w1s[i] = qf(W1l[i]);
        w2s[i] = qf(W2l[i]);
    }
    if (tid < 2 * CC) {
        b1s[tid] = qf(b1[l * 2 * CC + tid]);
        float rsv = rsqrtf(v1[l * 2 * CC + tid] + BN_EPS_F);
        float a = g1[l * 2 * CC + tid] * rsv;
        a1s[tid] = a;
        d1s[tid] = bb1[l * 2 * CC + tid] - m1[l * 2 * CC + tid] * a;
    }
    if (tid < CC) {
        b2s[tid] = qf(b2[l * CC + tid]);
        float ga = eg[tid] * rsqrtf(ev[tid] + BN_EPS_F);
        Es[tid] = eb[tid] - em[tid] * ga + GEN_EPS_F;
    }
    __syncthreads();

    int node = blockIdx.x * 128 + tid;
    if (node >= NN) return;

    float xq[CC];
    const float4* hp = (const float4*)(d_h2 + node * CC);
    #pragma unroll
    for (int i = 0; i < 8; i++) {
        float4 t4 = hp[i];
        xq[4 * i + 0] = qf(t4.x); xq[4 * i + 1] = qf(t4.y);
        xq[4 * i + 2] = qf(t4.z); xq[4 * i + 3] = qf(t4.w);
    }
    float acc2[CC];
    #pragma unroll
    for (int c = 0; c < CC; c++) acc2[c] = b2s[c];

    for (int j = 0; j < 2 * CC; j++) {
        float a = b1s[j];
        #pragma unroll
        for (int k = 0; k < CC; k++) a = fmaf(xq[k], w1s[k * 2 * CC + j], a);
        float z1 = qf(a);
        float zr = qf(fmaxf(fmaf(a1s[j], z1, d1s[j]), 0.0f));
        #pragma unroll
        for (int c = 0; c < CC; c++) acc2[c] = fmaf(zr, w2s[j * CC + c], acc2[c]);
    }
    bool emit_hb = (l < LL - 1);
    float tl2n = emit_hb ? __ldg(t + l + 1) * LOG2E_F : 0.0f;
    const float4* ip = (const float4*)(d_h + node * CC);
    float4* op = (float4*)(d_h + node * CC);
    float4* bp = (float4*)(d_hb + node * CC);
    #pragma unroll
    for (int c = 0; c < CC; c += 4) {
        float4 id4 = ip[c >> 2];
        float4 o;
        o.x = qf(acc2[c + 0]) + id4.x;
        o.y = qf(acc2[c + 1]) + id4.y;
        o.z = qf(acc2[c + 2]) + id4.z;
        o.w = qf(acc2[c + 3]) + id4.w;
        op[c >> 2] = o;
        if (emit_hb) {
            float4 hbv;
            hbv.x = (o.x + Es[c + 0]) * tl2n;
            hbv.y = (o.y + Es[c + 1]) * tl2n;
            hbv.z = (o.z + Es[c + 2]) * tl2n;
            hbv.w = (o.w + Es[c + 3]) * tl2n;
            bp[c >> 2] = hbv;
        }
    }
}

// ---------------- global mean pool ----------------------------------------------
__global__ void k_pool(const int* __restrict__ batch) {
    int lane = threadIdx.x & 31;
    int w = (blockIdx.x * blockDim.x + threadIdx.x) >> 5;
    const int CHUNK = 128;
    int i0 = w * CHUNK;
    if (i0 >= NN) return;
    int i1 = min(i0 + CHUNK, NN);
    int cur = batch[i0];
    float acc = 0.0f;
    for (int i = i0; i < i1; i++) {
        int g = batch[i];
        float val = d_h[i * CC + lane];
        if (g != cur) {
            atomicAdd(&d_pool[cur * CC + lane], acc);
            acc = 0.0f;
            cur = g;
        }
        acc += val;
    }
    atomicAdd(&d_pool[cur * CC + lane], acc);
}

__global__ void k_cnt(const int* __restrict__ batch) {
    int g = blockIdx.x * blockDim.x + threadIdx.x;
    if (g >= GG) return;
    int lo0 = 0, hi0 = NN;
    while (lo0 < hi0) { int mid = (lo0 + hi0) >> 1; if (batch[mid] < g) lo0 = mid + 1; else hi0 = mid; }
    int lo1 = lo0, hi1 = NN;
    while (lo1 < hi1) { int mid = (lo1 + hi1) >> 1; if (batch[mid] < g + 1) lo1 = mid + 1; else hi1 = mid; }
    d_cntf[g] = (float)(lo1 - lo0);
}

__global__ void k_final(const float* __restrict__ Wo, const float* __restrict__ bo,
                        float* __restrict__ out) {
    __shared__ float wq[CC];
    int tid = threadIdx.x;
    if (tid < CC) wq[tid] = qf(Wo[tid]);
    __syncthreads();
    int g = blockIdx.x * blockDim.x + tid;
    if (g >= GG) return;
    float cnt = fmaxf(d_cntf[g], 1.0f);
    float acc = qf(bo[0]);
    #pragma unroll
    for (int c = 0; c < CC; c++) {
        float pm = d_pool[g * CC + c] / cnt;
        acc = fmaf(qf(pm), wq[c], acc);
    }
    float o = qf(acc);
    float s = 1.0f / (1.0f + expf(-o));
    out[g] = qf(s);
}

// ---------------- launch ---------------------------------------------------------
extern "C" void kernel_launch(void* const* d_in, const int* in_sizes, int n_in,
                              void* d_out, int out_size) {
    const float* x    = (const float*)d_in[0];
    const float* ea   = (const float*)d_in[1];
    const float* Wn   = (const float*)d_in[2];
    const float* bn_  = (const float*)d_in[3];
    const float* We   = (const float*)d_in[4];
    const float* be   = (const float*)d_in[5];
    const float* bnng = (const float*)d_in[6];
    const float* bnnb = (const float*)d_in[7];
    const float* bnnm = (const float*)d_in[8];
    const float* bnnv = (const float*)d_in[9];
    const float* bneg = (const float*)d_in[10];
    const float* bneb = (const float*)d_in[11];
    const float* bnem = (const float*)d_in[12];
    const float* bnev = (const float*)d_in[13];
    const float* t    = (const float*)d_in[14];
    const float* W1   = (const float*)d_in[15];
    const float* b1   = (const float*)d_in[16];
    const float* g1   = (const float*)d_in[17];
    const float* bb1  = (const float*)d_in[18];
    const float* m1   = (const float*)d_in[19];
    const float* v1   = (const float*)d_in[20];
    const float* W2   = (const float*)d_in[21];
    const float* b2   = (const float*)d_in[22];
    const float* Wo   = (const float*)d_in[23];
    const float* bo   = (const float*)d_in[24];
    const int*   ei   = (const int*)d_in[25];
    const int*   batch= (const int*)d_in[26];
    float* out = (float*)d_out;

    k_pre<<<(EE + 255) / 256, 256>>>(x, Wn, bn_, bnng, bnnb, bnnm, bnnv,
                                     bneg, bneb, bnem, bnev, t, ei);
    k_scan<<<SCAN_NB, 1024>>>();
    k_edge_enc<<<(EE + 255) / 256, 256>>>(ea, We, be, ei);

    for (int l = 0; l < LL; l++) {
        k_agg<<<(NN + 7) / 8, 256>>>(t, l, bneg, bnev);
        k_mlp<<<(NN + 127) / 128, 128>>>(l, W1, b1, g1, bb1, m1, v1, W2, b2,
                                         bneg, bneb, bnem, bnev, t);
    }

    k_pool<<<98, 256>>>(batch);
    k_cnt<<<(GG + 255) / 256, 256>>>(batch);
    k_final<<<(GG + 255) / 256, 256>>>(Wo, bo, out);
}